// round 15
// baseline (speedup 1.0000x reference)
#include <cuda_runtime.h>
#include <cuda_fp16.h>
#include <cstdint>

// LSTM single step, B=64, H=I=O=2048.  out[64,6144] = concat(y, h_new, c_new).
// ONE kernel, 288 CTAs (all co-resident at 2 CTAs/SM), 3 phases:
//   0: convert concat(h,x) -> fp16 g_A (cooperative)
//   1: HMMA GEMM, fp16 accum dumped to fp32 every TWO k64 chunks (chain 4):
//      256 gate CTAs (split-K at h/x) + 32 y CTAs, 32 chunks,
//      8 warps = 2M x 2N x 2K, warp tile 32x32
//   2: partial-sum + biases + LSTM pointwise (fast-math) -> h, c
// Grid barriers: monotone-ticket atomics (replay-safe, deterministic).

#define KD 2048
#define NOUT 6144
#define NCTA 288u

__device__ __half g_A[64 * 4096];            // concat(h, x) fp16
__device__ float g_part[2][4 * 64 * KD];     // split-K gate partials
__device__ unsigned g_tk0, g_tk1;            // barrier tickets (monotone)

#define SWZ128(o) ((o) ^ (((o) >> 3) & 0x70))

__device__ __forceinline__ uint32_t smem_u32(const void* p) {
    uint32_t a;
    asm("{ .reg .u64 t; cvta.to.shared.u64 t, %1; cvt.u32.u64 %0, t; }"
        : "=r"(a) : "l"(p));
    return a;
}

#define LDSM4(r, addr)                                                       \
    asm volatile("ldmatrix.sync.aligned.m8n8.x4.shared.b16 {%0,%1,%2,%3}, [%4];" \
                 : "=r"((r)[0]), "=r"((r)[1]), "=r"((r)[2]), "=r"((r)[3])    \
                 : "r"(addr))
#define LDSM4T(r, addr)                                                      \
    asm volatile("ldmatrix.sync.aligned.m8n8.x4.trans.shared.b16 {%0,%1,%2,%3}, [%4];" \
                 : "=r"((r)[0]), "=r"((r)[1]), "=r"((r)[2]), "=r"((r)[3])    \
                 : "r"(addr))
#define MMA16816H(d, a, b0, b1)                                              \
    asm volatile("mma.sync.aligned.m16n8k16.row.col.f16.f16.f16.f16 "        \
                 "{%0,%1}, {%2,%3,%4,%5}, {%6,%7}, {%0,%1};"                 \
                 : "+r"((d)[0]), "+r"((d)[1])                                \
                 : "r"((a)[0]), "r"((a)[1]), "r"((a)[2]), "r"((a)[3]),       \
                   "r"(b0), "r"(b1))
#define CP_ASYNC16(saddr, gptr)                                              \
    asm volatile("cp.async.cg.shared.global [%0], [%1], 16;" :: "r"(saddr), "l"(gptr))
#define CP_COMMIT() asm volatile("cp.async.commit_group;" ::: "memory")
#define CP_WAIT1()  asm volatile("cp.async.wait_group 1;" ::: "memory")

// SMEM (relative to 1KB-aligned base):
//   A stages (3): s*8192           (64 rows x 128B fp16)
//   B stages (2): 24576 + s*8192
#define A_OFF(s)  ((uint32_t)(s) * 8192u)
#define B_OFF(s)  (24576u + (uint32_t)(s) * 8192u)
#define SMEM_BYTES (40960 + 1024)

__device__ __forceinline__ float fast_sig(float v) {
    return 1.f / (1.f + __expf(-v));
}
__device__ __forceinline__ float fast_tanh(float v) {
    return 2.f / (1.f + __expf(-2.f * v)) - 1.f;
}

// Grid barrier: all 288 CTAs co-resident (2/SM by launch_bounds + smem), so
// spinning is deadlock-free.  Monotone ticket => replay-safe, no reset.
__device__ __forceinline__ void grid_barrier(unsigned* ctr) {
    __threadfence();
    __syncthreads();
    if (threadIdx.x == 0) {
        unsigned my = atomicAdd(ctr, 1u);
        unsigned target = (my / NCTA + 1u) * NCTA;
        while (*(volatile unsigned*)ctr < target) __nanosleep(64);
    }
    __syncthreads();
    __threadfence();
}

// ---------------------------------------------------------------------------
__global__ void __launch_bounds__(256, 2) lstm_fused(
    const float* __restrict__ h_prev, const float* __restrict__ x_in,
    const float* __restrict__ c_prev,
    const float* __restrict__ Wfh, const float* __restrict__ Wfx,
    const float* __restrict__ Wih, const float* __restrict__ Wix,
    const float* __restrict__ Wch, const float* __restrict__ Wcx,
    const float* __restrict__ Woh, const float* __restrict__ Wox,
    const float* __restrict__ Wy,
    const float* __restrict__ bf_, const float* __restrict__ bi_,
    const float* __restrict__ bc_, const float* __restrict__ bo_,
    const float* __restrict__ by_,
    float* __restrict__ out)
{
    extern __shared__ char smem_raw[];
    uint32_t su0 = smem_u32(smem_raw);
    const uint32_t su = (su0 + 1023u) & ~1023u;
    char* sm = smem_raw + (su - su0);

    const int t = threadIdx.x, bx = blockIdx.x;
    const int lane = t & 31, wid = t >> 5;
    const int kh = wid >> 2, mi = (wid >> 1) & 1, ni = wid & 1;
    const int lr = lane & 15, lc = lane >> 4;

    // ------------- phase 0: build g_A = fp16 concat(h, x) ------------------
    {
        int u = bx * 256 + t;                   // 73728 threads, 65536 units
        if (u < 65536) {
            int idx = u * 4;
            int r = idx >> 12, k = idx & 4095;
            const float* src = (k < 2048) ? (h_prev + r * 2048 + k)
                                          : (x_in + r * 2048 + (k - 2048));
            float4 v = *(const float4*)src;
            __half2 p0 = __floats2half2_rn(v.x, v.y);
            __half2 p1 = __floats2half2_rn(v.z, v.w);
            *(uint2*)(g_A + idx) = make_uint2(*(uint32_t*)&p0, *(uint32_t*)&p1);
        }
    }
    grid_barrier(&g_tk0);

    // ------------- phase 1: GEMM ------------------------------------------
    const float* WH[4] = {Wfh, Wih, Wch, Woh};
    const float* WX[4] = {Wfx, Wix, Wcx, Wox};

    const bool isY = (bx >= 256);
    const float *W;
    float* Cout;
    int jj, ldc, aCol0;
    if (!isY) {
        const int tile = bx >> 1, kk = bx & 1;
        const int g = tile >> 5;
        jj = (tile & 31) * 64;
        W = kk ? WX[g] : WH[g];
        aCol0 = kk * 2048;
        Cout = g_part[kk] + g * 64 * KD + jj;
        ldc = KD;
    } else {
        jj = (bx - 256) * 64;
        W = Wy;
        aCol0 = 0;
        Cout = out + jj;
        ldc = NOUT;
    }

    const int brow = t >> 2, bseg = t & 3;      // B staging: 64 k-rows x 4 segs

    float master[2][4][4];
    uint32_t acch[2][4][2];
#pragma unroll
    for (int mf = 0; mf < 2; mf++)
#pragma unroll
        for (int j = 0; j < 4; j++) {
#pragma unroll
            for (int q = 0; q < 4; q++) master[mf][j][q] = 0.f;
            acch[mf][j][0] = 0u; acch[mf][j][1] = 0u;
        }

    auto issueA = [&](int c, int s) {
        const int aK = aCol0 + c * 64;
#pragma unroll
        for (int ui = 0; ui < 2; ui++) {
            const int u = t * 2 + ui;
            const int row = u >> 3, cs = u & 7;
            const uint32_t saddr = su + A_OFF(s) + SWZ128(row * 128 + cs * 16);
            const __half* gsrc = g_A + (size_t)row * 4096 + aK + cs * 8;
            CP_ASYNC16(saddr, gsrc);
        }
    };
    auto ldgB = [&](int c, float4* rb) {
        const float* src = W + (size_t)(c * 64 + brow) * 2048 + jj + bseg * 16;
        rb[0] = *(const float4*)(src + 0);
        rb[1] = *(const float4*)(src + 4);
        rb[2] = *(const float4*)(src + 8);
        rb[3] = *(const float4*)(src + 12);
    };

    issueA(0, 0);
    CP_COMMIT();
    float4 rb[4];
    ldgB(0, rb);

    for (int c = 0; c < 32; ++c) {
        const int s = c & 1;

        // Convert + STS B(c) fp32 -> fp16.  (Consumes rb.)
        {
            __half2 p[8];
            p[0] = __floats2half2_rn(rb[0].x, rb[0].y);
            p[1] = __floats2half2_rn(rb[0].z, rb[0].w);
            p[2] = __floats2half2_rn(rb[1].x, rb[1].y);
            p[3] = __floats2half2_rn(rb[1].z, rb[1].w);
            p[4] = __floats2half2_rn(rb[2].x, rb[2].y);
            p[5] = __floats2half2_rn(rb[2].z, rb[2].w);
            p[6] = __floats2half2_rn(rb[3].x, rb[3].y);
            p[7] = __floats2half2_rn(rb[3].z, rb[3].w);
            const uint32_t rbse = brow * 128 + bseg * 32;
            *(uint4*)(sm + B_OFF(s) + SWZ128(rbse)) =
                make_uint4(*(uint32_t*)&p[0], *(uint32_t*)&p[1],
                           *(uint32_t*)&p[2], *(uint32_t*)&p[3]);
            *(uint4*)(sm + B_OFF(s) + SWZ128(rbse + 16)) =
                make_uint4(*(uint32_t*)&p[4], *(uint32_t*)&p[5],
                           *(uint32_t*)&p[6], *(uint32_t*)&p[7]);
        }

        // Prefetch chunk c+1 BEFORE the wait/barrier; LDG (longest latency)
        // issued first.
        if (c + 1 < 32) {
            ldgB(c + 1, rb);
            issueA(c + 1, (c + 1) % 3);
        }
        CP_COMMIT();
        CP_WAIT1();           // A(c) resident
        __syncthreads();

        // Compute chunk c, this warp's k32 half: 2 ks steps x 8 MMAs.
        {
            const int sa = c % 3;
            const uint32_t aBase = su + A_OFF(sa);
            const uint32_t bBase = su + B_OFF(s);
#pragma unroll
            for (int ksl = 0; ksl < 2; ksl++) {
                const int ks = kh * 2 + ksl;
                uint32_t a0[4], a1[4];
                LDSM4(a0, aBase + SWZ128((mi * 32 + lr) * 128 + ks * 32 + lc * 16));
                LDSM4(a1, aBase + SWZ128((mi * 32 + 16 + lr) * 128 + ks * 32 + lc * 16));
                const uint32_t brw = (ks * 16 + lr) * 128 + ni * 64;
                uint32_t b0[4], b1[4];
                LDSM4T(b0, bBase + SWZ128(brw + lc * 16));
                LDSM4T(b1, bBase + SWZ128(brw + 32 + lc * 16));
                MMA16816H(acch[0][0], a0, b0[0], b0[1]);
                MMA16816H(acch[0][1], a0, b0[2], b0[3]);
                MMA16816H(acch[0][2], a0, b1[0], b1[1]);
                MMA16816H(acch[0][3], a0, b1[2], b1[3]);
                MMA16816H(acch[1][0], a1, b0[0], b0[1]);
                MMA16816H(acch[1][1], a1, b0[2], b0[3]);
                MMA16816H(acch[1][2], a1, b1[0], b1[1]);
                MMA16816H(acch[1][3], a1, b1[2], b1[3]);
            }
            // dump to fp32 masters every 2 chunks (fp16 chain length 4)
            if (c & 1) {
#pragma unroll
                for (int mf = 0; mf < 2; mf++)
#pragma unroll
                    for (int j = 0; j < 4; j++) {
                        float2 lo = __half22float2(*(__half2*)&acch[mf][j][0]);
                        float2 hi = __half22float2(*(__half2*)&acch[mf][j][1]);
                        master[mf][j][0] += lo.x; master[mf][j][1] += lo.y;
                        master[mf][j][2] += hi.x; master[mf][j][3] += hi.y;
                        acch[mf][j][0] = 0u; acch[mf][j][1] = 0u;
                    }
            }
        }
    }

    // GEMM epilogue: combine the two k-halves via smem, then write.
    __syncthreads();                       // A/B buffers now free
    float* ex = (float*)sm;                // 4 tiles x 32x33 fp32 (16.9 KB)
    const int tl = mi * 2 + ni;
    if (kh == 1) {
#pragma unroll
        for (int mf = 0; mf < 2; mf++) {
            const int mb = mf * 16 + (lane >> 2);
#pragma unroll
            for (int j = 0; j < 4; j++) {
                const int nb = j * 8 + (lane & 3) * 2;
                float* p = ex + tl * 1056 + mb * 33 + nb;
                p[0]          = master[mf][j][0];
                p[1]          = master[mf][j][1];
                p[8 * 33]     = master[mf][j][2];
                p[8 * 33 + 1] = master[mf][j][3];
            }
        }
    }
    __syncthreads();
    if (kh == 0) {
#pragma unroll
        for (int mf = 0; mf < 2; mf++) {
            const int mb = mf * 16 + (lane >> 2);
            const int m0 = mi * 32 + mb;
#pragma unroll
            for (int j = 0; j < 4; j++) {
                const int nb = j * 8 + (lane & 3) * 2;
                const int n = ni * 32 + nb;
                const float* p = ex + tl * 1056 + mb * 33 + nb;
                float b0 = 0.f, b1 = 0.f;
                if (isY) { b0 = by_[jj + n]; b1 = by_[jj + n + 1]; }
                *(float2*)(Cout + (size_t)m0 * ldc + n) = make_float2(
                    master[mf][j][0] + p[0] + b0,
                    master[mf][j][1] + p[1] + b1);
                *(float2*)(Cout + (size_t)(m0 + 8) * ldc + n) = make_float2(
                    master[mf][j][2] + p[8 * 33] + b0,
                    master[mf][j][3] + p[8 * 33 + 1] + b1);
            }
        }
    }

    grid_barrier(&g_tk1);

    // ------------- phase 2: pointwise LSTM (partials L2-hot) ---------------
    {
        int u = bx * 256 + t;                   // 65536 float2 units
        if (u < 65536) {
            const int idx = u * 2;
            const int r = idx >> 11, j = idx & 2047;
            float2 gf = *(const float2*)&g_part[0][0 * 64 * KD + idx];
            float2 gi = *(const float2*)&g_part[0][1 * 64 * KD + idx];
            float2 gc = *(const float2*)&g_part[0][2 * 64 * KD + idx];
            float2 go = *(const float2*)&g_part[0][3 * 64 * KD + idx];
            float2 q;
            q = *(const float2*)&g_part[1][0 * 64 * KD + idx]; gf.x += q.x; gf.y += q.y;
            q = *(const float2*)&g_part[1][1 * 64 * KD + idx]; gi.x += q.x; gi.y += q.y;
            q = *(const float2*)&g_part[1][2 * 64 * KD + idx]; gc.x += q.x; gc.y += q.y;
            q = *(const float2*)&g_part[1][3 * 64 * KD + idx]; go.x += q.x; go.y += q.y;
            float2 vbf = *(const float2*)(bf_ + j);
            float2 vbi = *(const float2*)(bi_ + j);
            float2 vbc = *(const float2*)(bc_ + j);
            float2 vbo = *(const float2*)(bo_ + j);
            float2 cp  = *(const float2*)(c_prev + idx);
            float ga[2] = {gf.x + vbf.x, gf.y + vbf.y};
            float gb[2] = {gi.x + vbi.x, gi.y + vbi.y};
            float gg[2] = {gc.x + vbc.x, gc.y + vbc.y};
            float gd[2] = {go.x + vbo.x, go.y + vbo.y};
            float cpa[2] = {cp.x, cp.y};
            float hh[2], cc[2];
#pragma unroll
            for (int e = 0; e < 2; e++) {
                float f  = fast_sig(ga[e]);
                float ii = fast_sig(gb[e]);
                float ct = fast_tanh(gg[e]);
                float o  = fast_sig(gd[e]);
                cc[e] = f * cpa[e] + ii * ct;
                hh[e] = o * fast_tanh(cc[e]);
            }
            *(float2*)(out + r * NOUT + 2048 + j) = make_float2(hh[0], hh[1]);
            *(float2*)(out + r * NOUT + 4096 + j) = make_float2(cc[0], cc[1]);
        }
    }
}

// ---------------------------------------------------------------------------
extern "C" void kernel_launch(void* const* d_in, const int* in_sizes, int n_in,
                              void* d_out, int out_size) {
    const float* x      = (const float*)d_in[0];
    const float* h_prev = (const float*)d_in[1];
    const float* c_prev = (const float*)d_in[2];
    const float* Wfh = (const float*)d_in[3];
    const float* Wfx = (const float*)d_in[4];
    const float* bf  = (const float*)d_in[5];
    const float* Wih = (const float*)d_in[6];
    const float* Wix = (const float*)d_in[7];
    const float* bi  = (const float*)d_in[8];
    const float* Woh = (const float*)d_in[9];
    const float* Wox = (const float*)d_in[10];
    const float* bo  = (const float*)d_in[11];
    const float* Wch = (const float*)d_in[12];
    const float* Wcx = (const float*)d_in[13];
    const float* bc  = (const float*)d_in[14];
    const float* Wy  = (const float*)d_in[15];
    const float* by  = (const float*)d_in[16];
    float* out = (float*)d_out;

    static int smem_set = 0;
    if (!smem_set) {
        cudaFuncSetAttribute(lstm_fused, cudaFuncAttributeMaxDynamicSharedMemorySize,
                             SMEM_BYTES);
        smem_set = 1;
    }

    lstm_fused<<<288, 256, SMEM_BYTES>>>(h_prev, x, c_prev,
                                         Wfh, Wfx, Wih, Wix, Wch, Wcx, Woh, Wox,
                                         Wy, bf, bi, bc, bo, by, out);
}